// round 5
// baseline (speedup 1.0000x reference)
#include <cuda_runtime.h>

#define HIDDEN   1024
#define BATCH    2
#define SEQ      2048
#define NHEADS   16
#define HDIM     64
#define MROWS    (BATCH * SEQ)   // 4096

// ---------------------------------------------------------------------------
// Scratch (static device globals — no runtime allocation allowed)
// ---------------------------------------------------------------------------
__device__ __align__(256) float g_q[BATCH * NHEADS * SEQ * HDIM];   // 16 MB
__device__ __align__(256) float g_k[BATCH * NHEADS * SEQ * HDIM];   // 16 MB
__device__ __align__(256) float g_v[BATCH * NHEADS * SEQ * HDIM];   // 16 MB
__device__ __align__(256) float g_ao[MROWS * HIDDEN];               // 16 MB

// ---------------------------------------------------------------------------
// SGEMM: C[M,N] = A[M,K] @ B[N,K]^T + bias[N]
//   mode 0: plain write to C (used for O-projection; A==nullptr -> read g_ao)
//   mode 1: scatter epilogue into g_q/g_k/g_v head-major layout
// Tiling: BM=128, BN=128, BK=16, 256 threads, 8x8 microtile per thread.
// ---------------------------------------------------------------------------
#define BM  128
#define BN  128
#define BKK 16

__global__ __launch_bounds__(256, 2)
void sgemm_kernel(const float* __restrict__ A, const float* __restrict__ Bm,
                  const float* __restrict__ bias, float* __restrict__ C,
                  int M, int N, int K, int mode)
{
    __shared__ float As[BKK][BM + 4];
    __shared__ float Bs[BKK][BN + 4];

    const int tid = threadIdx.x;
    const int tx  = tid & 15;      // 0..15 -> N microtile
    const int ty  = tid >> 4;      // 0..15 -> M microtile
    const int bm  = blockIdx.y * BM;
    const int bn  = blockIdx.x * BN;

    const float* Aeff = A ? A : g_ao;

    // Loader mapping: each thread loads 2 float4 from A and 2 from B per k-step
    const int ar = tid >> 2;           // 0..63
    const int ac = (tid & 3) << 2;     // 0,4,8,12
    const float* ap = Aeff + (size_t)(bm + ar) * K + ac;
    const float* bp = Bm   + (size_t)(bn + ar) * K + ac;

    float acc[8][8];
#pragma unroll
    for (int i = 0; i < 8; i++)
#pragma unroll
        for (int j = 0; j < 8; j++) acc[i][j] = 0.f;

    for (int k0 = 0; k0 < K; k0 += BKK) {
        float4 a0 = *(const float4*)(ap);
        float4 a1 = *(const float4*)(ap + (size_t)64 * K);
        float4 b0 = *(const float4*)(bp);
        float4 b1 = *(const float4*)(bp + (size_t)64 * K);
        ap += BKK; bp += BKK;

        __syncthreads();   // previous compute phase done reading smem
        As[ac + 0][ar]      = a0.x; As[ac + 1][ar]      = a0.y;
        As[ac + 2][ar]      = a0.z; As[ac + 3][ar]      = a0.w;
        As[ac + 0][ar + 64] = a1.x; As[ac + 1][ar + 64] = a1.y;
        As[ac + 2][ar + 64] = a1.z; As[ac + 3][ar + 64] = a1.w;
        Bs[ac + 0][ar]      = b0.x; Bs[ac + 1][ar]      = b0.y;
        Bs[ac + 2][ar]      = b0.z; Bs[ac + 3][ar]      = b0.w;
        Bs[ac + 0][ar + 64] = b1.x; Bs[ac + 1][ar + 64] = b1.y;
        Bs[ac + 2][ar + 64] = b1.z; Bs[ac + 3][ar + 64] = b1.w;
        __syncthreads();

#pragma unroll
        for (int kk = 0; kk < BKK; kk++) {
            float ra[8], rb[8];
            *(float4*)&ra[0] = *(const float4*)&As[kk][ty * 8];
            *(float4*)&ra[4] = *(const float4*)&As[kk][ty * 8 + 4];
            *(float4*)&rb[0] = *(const float4*)&Bs[kk][tx * 8];
            *(float4*)&rb[4] = *(const float4*)&Bs[kk][tx * 8 + 4];
#pragma unroll
            for (int i = 0; i < 8; i++)
#pragma unroll
                for (int j = 0; j < 8; j++)
                    acc[i][j] = fmaf(ra[i], rb[j], acc[i][j]);
        }
    }

    float rbias[8];
#pragma unroll
    for (int j = 0; j < 8; j++) rbias[j] = bias[bn + tx * 8 + j];

    if (mode == 0) {
#pragma unroll
        for (int i = 0; i < 8; i++) {
            const int row = bm + ty * 8 + i;
            float4 v0, v1;
            v0.x = acc[i][0] + rbias[0]; v0.y = acc[i][1] + rbias[1];
            v0.z = acc[i][2] + rbias[2]; v0.w = acc[i][3] + rbias[3];
            v1.x = acc[i][4] + rbias[4]; v1.y = acc[i][5] + rbias[5];
            v1.z = acc[i][6] + rbias[6]; v1.w = acc[i][7] + rbias[7];
            *(float4*)&C[(size_t)row * N + bn + tx * 8]     = v0;
            *(float4*)&C[(size_t)row * N + bn + tx * 8 + 4] = v1;
        }
    } else {
        // Scatter into g_q/g_k/g_v as [b][h][n][hd]
#pragma unroll
        for (int i = 0; i < 8; i++) {
            const int m = bm + ty * 8 + i;
            const int b = m >> 11;          // /SEQ (2048)
            const int n = m & 2047;
#pragma unroll
            for (int jj = 0; jj < 8; jj += 4) {
                const int e    = bn + tx * 8 + jj;
                const int part = e >> 10;       // 0:q 1:k 2:v
                const int c    = e & 1023;
                const int h    = c >> 6;
                const int hd   = c & 63;        // hd .. hd+3 stay in same head
                float* dst = (part == 0) ? g_q : ((part == 1) ? g_k : g_v);
                float4 v;
                v.x = acc[i][jj + 0] + rbias[jj + 0];
                v.y = acc[i][jj + 1] + rbias[jj + 1];
                v.z = acc[i][jj + 2] + rbias[jj + 2];
                v.w = acc[i][jj + 3] + rbias[jj + 3];
                *(float4*)&dst[(((size_t)(b * NHEADS + h) * SEQ) + n) * HDIM + hd] = v;
            }
        }
    }
}

// ---------------------------------------------------------------------------
// Fused flash attention (fp32, online softmax).
// Block: 64 queries x full HDIM=64 of one (b,h). 256 threads, 4x4 microtiles.
// Smem (dynamic, 52224 B): Qt[d][q], Kt[d][k] (reused as P[q][k]), Vs[k][d],
// all stride 68 floats.
// ---------------------------------------------------------------------------
#define AST 68
#define ATTN_SMEM (3 * 64 * AST * 4)

__global__ __launch_bounds__(256)
void attn_kernel()
{
    extern __shared__ float sm[];
    float* Qt = sm;                 // [d][q]
    float* Kt = sm + 64 * AST;      // [d][k], then reused as P[q][k]
    float* Vs = sm + 2 * 64 * AST;  // [k][d]

    const int tid = threadIdx.x;
    const int tx  = tid & 15;       // key / d-column microtile
    const int ty  = tid >> 4;       // query microtile
    const int qt  = blockIdx.x;     // 0..31
    const int h   = blockIdx.y;
    const int b   = blockIdx.z;

    const size_t head_off = (size_t)(b * NHEADS + h) * SEQ * HDIM;
    const float* qp = g_q + head_off + (size_t)qt * 64 * HDIM;
    const float* kp = g_k + head_off;
    const float* vp = g_v + head_off;

    const int lr = tid >> 2;            // 0..63
    const int lc = (tid & 3) << 4;      // 0,16,32,48

    // Load Q tile transposed: Qt[d][q]
#pragma unroll
    for (int u = 0; u < 4; u++) {
        float4 v = *(const float4*)(qp + (size_t)lr * HDIM + lc + u * 4);
        Qt[(lc + u * 4 + 0) * AST + lr] = v.x;
        Qt[(lc + u * 4 + 1) * AST + lr] = v.y;
        Qt[(lc + u * 4 + 2) * AST + lr] = v.z;
        Qt[(lc + u * 4 + 3) * AST + lr] = v.w;
    }

    float acc[4][4];
    float mrow[4], lrow[4];
#pragma unroll
    for (int i = 0; i < 4; i++) {
        mrow[i] = -3.0e38f;
        lrow[i] = 0.f;
#pragma unroll
        for (int j = 0; j < 4; j++) acc[i][j] = 0.f;
    }

    for (int kt = 0; kt < SEQ / 64; kt++) {
        float4 kreg[4], vreg[4];
        const float* kr = kp + (size_t)kt * 64 * HDIM + (size_t)lr * HDIM + lc;
        const float* vr = vp + (size_t)kt * 64 * HDIM + (size_t)lr * HDIM + lc;
#pragma unroll
        for (int u = 0; u < 4; u++) {
            kreg[u] = *(const float4*)(kr + u * 4);
            vreg[u] = *(const float4*)(vr + u * 4);
        }

        __syncthreads();   // previous PV done with Kt/Vs (and Qt visible on iter 0)
#pragma unroll
        for (int u = 0; u < 4; u++) {
            Kt[(lc + u * 4 + 0) * AST + lr] = kreg[u].x;
            Kt[(lc + u * 4 + 1) * AST + lr] = kreg[u].y;
            Kt[(lc + u * 4 + 2) * AST + lr] = kreg[u].z;
            Kt[(lc + u * 4 + 3) * AST + lr] = kreg[u].w;
            *(float4*)(Vs + lr * AST + lc + u * 4) = vreg[u];
        }
        __syncthreads();

        // S = Q K^T (4x4 per thread)
        float s[4][4];
#pragma unroll
        for (int i = 0; i < 4; i++)
#pragma unroll
            for (int j = 0; j < 4; j++) s[i][j] = 0.f;

#pragma unroll 8
        for (int d = 0; d < HDIM; d++) {
            float4 q4 = *(const float4*)(Qt + d * AST + ty * 4);
            float4 k4 = *(const float4*)(Kt + d * AST + tx * 4);
            float qa[4] = {q4.x, q4.y, q4.z, q4.w};
            float ka[4] = {k4.x, k4.y, k4.z, k4.w};
#pragma unroll
            for (int i = 0; i < 4; i++)
#pragma unroll
                for (int j = 0; j < 4; j++)
                    s[i][j] = fmaf(qa[i], ka[j], s[i][j]);
        }

        // Online softmax update (rows owned by 16-lane groups sharing ty)
#pragma unroll
        for (int i = 0; i < 4; i++) {
#pragma unroll
            for (int j = 0; j < 4; j++) s[i][j] *= 0.125f;   // 1/sqrt(64)
            float rm = fmaxf(fmaxf(s[i][0], s[i][1]), fmaxf(s[i][2], s[i][3]));
#pragma unroll
            for (int off = 8; off > 0; off >>= 1)
                rm = fmaxf(rm, __shfl_xor_sync(0xffffffffu, rm, off, 16));
            const float mn   = fmaxf(mrow[i], rm);
            const float corr = __expf(mrow[i] - mn);
            float rs = 0.f;
#pragma unroll
            for (int j = 0; j < 4; j++) {
                s[i][j] = __expf(s[i][j] - mn);
                rs += s[i][j];
            }
#pragma unroll
            for (int off = 8; off > 0; off >>= 1)
                rs += __shfl_xor_sync(0xffffffffu, rs, off, 16);
            lrow[i] = lrow[i] * corr + rs;
            mrow[i] = mn;
#pragma unroll
            for (int j = 0; j < 4; j++) acc[i][j] *= corr;
        }

        __syncthreads();   // everyone done reading Kt as K-tile
        // Store P into Kt as [q][k] (float4, conflict-free)
#pragma unroll
        for (int i = 0; i < 4; i++) {
            float4 pv = make_float4(s[i][0], s[i][1], s[i][2], s[i][3]);
            *(float4*)(Kt + (ty * 4 + i) * AST + tx * 4) = pv;
        }
        __syncthreads();

        // O += P V  (k unrolled by 4)
#pragma unroll 4
        for (int k0 = 0; k0 < 64; k0 += 4) {
            float P[4][4], V[4][4];
#pragma unroll
            for (int i = 0; i < 4; i++) {
                float4 p4 = *(const float4*)(Kt + (ty * 4 + i) * AST + k0);
                P[i][0] = p4.x; P[i][1] = p4.y; P[i][2] = p4.z; P[i][3] = p4.w;
            }
#pragma unroll
            for (int u = 0; u < 4; u++) {
                float4 v4 = *(const float4*)(Vs + (k0 + u) * AST + tx * 4);
                V[u][0] = v4.x; V[u][1] = v4.y; V[u][2] = v4.z; V[u][3] = v4.w;
            }
#pragma unroll
            for (int i = 0; i < 4; i++)
#pragma unroll
                for (int j = 0; j < 4; j++) {
                    acc[i][j] = fmaf(P[i][0], V[0][j], acc[i][j]);
                    acc[i][j] = fmaf(P[i][1], V[1][j], acc[i][j]);
                    acc[i][j] = fmaf(P[i][2], V[2][j], acc[i][j]);
                    acc[i][j] = fmaf(P[i][3], V[3][j], acc[i][j]);
                }
        }
    }

    // Normalize and write to g_ao[b*SEQ+n][h*64+d]
#pragma unroll
    for (int i = 0; i < 4; i++) {
        const float inv = 1.0f / lrow[i];
        float4 o;
        o.x = acc[i][0] * inv; o.y = acc[i][1] * inv;
        o.z = acc[i][2] * inv; o.w = acc[i][3] * inv;
        const size_t row = (size_t)b * SEQ + qt * 64 + ty * 4 + i;
        *(float4*)&g_ao[row * HIDDEN + h * HDIM + tx * 4] = o;
    }
}

// ---------------------------------------------------------------------------
// Launch
// ---------------------------------------------------------------------------
extern "C" void kernel_launch(void* const* d_in, const int* in_sizes, int n_in,
                              void* d_out, int out_size)
{
    const float* x    = (const float*)d_in[0];
    const float* Wqkv = (const float*)d_in[1];
    const float* bqkv = (const float*)d_in[2];
    const float* Wo   = (const float*)d_in[3];
    const float* bo   = (const float*)d_in[4];
    float* out = (float*)d_out;

    cudaFuncSetAttribute(attn_kernel,
                         cudaFuncAttributeMaxDynamicSharedMemorySize, ATTN_SMEM);

    // QKV projection + head scatter
    dim3 gq(3 * HIDDEN / BN, MROWS / BM);
    sgemm_kernel<<<gq, 256>>>(x, Wqkv, bqkv, nullptr,
                              MROWS, 3 * HIDDEN, HIDDEN, 1);

    // Fused attention
    attn_kernel<<<dim3(SEQ / 64, NHEADS, BATCH), 256, ATTN_SMEM>>>();

    // Output projection (reads g_ao)
    dim3 go(HIDDEN / BN, MROWS / BM);
    sgemm_kernel<<<go, 256>>>(nullptr, Wo, bo, out,
                              MROWS, HIDDEN, HIDDEN, 0);
}

// round 9
// speedup vs baseline: 1.3747x; 1.3747x over previous
#include <cuda_runtime.h>
#include <cuda_bf16.h>
#include <cstdint>

#define HIDDEN   1024
#define BATCH    2
#define SEQ      2048
#define NHEADS   16
#define HDIM     64
#define MROWS    (BATCH * SEQ)   // 4096
#define KDIM     1024
#define K3       (3 * KDIM)      // 3072 (split-bf16 concatenated K)

// ---------------------------------------------------------------------------
// Scratch (static device globals — no runtime allocation allowed)
// ---------------------------------------------------------------------------
__device__ __align__(256) float g_q [BATCH * NHEADS * SEQ * HDIM];
__device__ __align__(256) float g_k [BATCH * NHEADS * SEQ * HDIM];
__device__ __align__(256) float g_v [BATCH * NHEADS * SEQ * HDIM];
__device__ __align__(256) float g_ao[MROWS * HIDDEN];

// Split-bf16 concatenated operands:
//   A-side rows: [hi | lo | hi]   (K3 columns)
//   B-side rows: [hi | hi | lo]
__device__ __align__(256) __nv_bfloat16 g_a3x[MROWS * K3];        // x split
__device__ __align__(256) __nv_bfloat16 g_a3o[MROWS * K3];        // attn-out split
__device__ __align__(256) __nv_bfloat16 g_b3q[3 * HIDDEN * K3];   // W_qkv split
__device__ __align__(256) __nv_bfloat16 g_b3o[HIDDEN * K3];       // W_o split

// ---------------------------------------------------------------------------
// PTX helpers (all baseline-sm_100 safe: cp.async, ldmatrix, mma.sync)
// ---------------------------------------------------------------------------
__device__ __forceinline__ uint32_t smem_u32(const void* p) {
    uint32_t a;
    asm("{ .reg .u64 t; cvta.to.shared.u64 t, %1; cvt.u32.u64 %0, t; }" : "=r"(a) : "l"(p));
    return a;
}

#define CP_ASYNC16(dst, src) \
    asm volatile("cp.async.cg.shared.global [%0], [%1], 16;" :: "r"(dst), "l"(src) : "memory")
#define CP_COMMIT() asm volatile("cp.async.commit_group;" ::: "memory")
#define CP_WAIT(n)  asm volatile("cp.async.wait_group %0;" :: "n"(n) : "memory")

#define LDSM_X4(r0, r1, r2, r3, addr) \
    asm volatile("ldmatrix.sync.aligned.m8n8.x4.shared.b16 {%0,%1,%2,%3}, [%4];" \
        : "=r"(r0), "=r"(r1), "=r"(r2), "=r"(r3) : "r"(addr))

#define MMA_BF16(d, a, b0, b1) \
    asm volatile("mma.sync.aligned.m16n8k16.row.col.f32.bf16.bf16.f32 " \
        "{%0,%1,%2,%3}, {%4,%5,%6,%7}, {%8,%9}, {%0,%1,%2,%3};" \
        : "+f"((d)[0]), "+f"((d)[1]), "+f"((d)[2]), "+f"((d)[3]) \
        : "r"((a)[0]), "r"((a)[1]), "r"((a)[2]), "r"((a)[3]), "r"(b0), "r"(b1))

// ---------------------------------------------------------------------------
// fp32 -> split-bf16 concatenated layout.
// dst_sel: 0 = g_a3x (src=x), 1 = g_b3q (src=Wqkv), 2 = g_b3o (src=Wo),
//          3 = g_a3o (src = g_ao, passed src ignored)
// A layout: hi @ c, c+2048 ; lo @ c+1024
// B layout: hi @ c, c+1024 ; lo @ c+2048
// ---------------------------------------------------------------------------
__global__ void split3_kernel(const float4* __restrict__ src, int dst_sel, int n4)
{
    int i = blockIdx.x * blockDim.x + threadIdx.x;
    if (i >= n4) return;
    const float4* s = src ? src : (const float4*)g_ao;
    __nv_bfloat16* dst = (dst_sel == 0) ? g_a3x :
                         (dst_sel == 1) ? g_b3q :
                         (dst_sel == 2) ? g_b3o : g_a3o;
    const int off_hi1 = (dst_sel == 1 || dst_sel == 2) ? 1024 : 2048;
    const int off_lo  = (dst_sel == 1 || dst_sel == 2) ? 2048 : 1024;

    const int r = i >> 8;            // 256 float4 per 1024-col source row
    const int c = (i & 255) << 2;    // element column within row

    float4 v = s[i];
    __nv_bfloat162 hA = __floats2bfloat162_rn(v.x, v.y);
    __nv_bfloat162 hB = __floats2bfloat162_rn(v.z, v.w);
    __nv_bfloat162 lA = __floats2bfloat162_rn(v.x - __low2float(hA), v.y - __high2float(hA));
    __nv_bfloat162 lB = __floats2bfloat162_rn(v.z - __low2float(hB), v.w - __high2float(hB));
    uint2 H, L;
    H.x = *reinterpret_cast<const uint32_t*>(&hA);
    H.y = *reinterpret_cast<const uint32_t*>(&hB);
    L.x = *reinterpret_cast<const uint32_t*>(&lA);
    L.y = *reinterpret_cast<const uint32_t*>(&lB);

    uint2* base = (uint2*)(dst + (size_t)r * K3);
    base[(c) >> 2]           = H;
    base[(off_hi1 + c) >> 2] = H;
    base[(off_lo  + c) >> 2] = L;
}

// ---------------------------------------------------------------------------
// bf16 mma.sync GEMM: C[M,N] = A3[M,K3] @ B3[N,K3]^T + bias
// 128x128 tile, BK=64, 3-stage cp.async pipeline, 256 threads (8 warps: 2Mx4N),
// warp tile 64x32 via m16n8k16 (4 m-frags x 4 n-frags).
// qkv=1: A=g_a3x, B=g_b3q, scatter epilogue into g_q/g_k/g_v head-major.
// qkv=0: A=g_a3o, B=g_b3o, write C (ldc=1024) + bias.
// ---------------------------------------------------------------------------
#define BK      64
#define NSTG    3
#define KC      (K3 / BK)          // 48
#define TILEB   (128 * BK * 2)     // 16384 B per operand tile
#define STAGEB  (2 * TILEB)        // 32768
#define GEMM_SMEM (NSTG * STAGEB)  // 98304

__global__ __launch_bounds__(256, 1)
void gemm_mma(const float* __restrict__ bias, float* __restrict__ C, int qkv)
{
    extern __shared__ __align__(1024) char smem[];
    const uint32_t sb = smem_u32(smem);

    const int tid  = threadIdx.x;
    const int lane = tid & 31;
    const int wid  = tid >> 5;
    const int wm   = wid & 1;       // 0..1 (64 M rows each)
    const int wn   = wid >> 1;      // 0..3 (32 N cols each)
    const int bm   = blockIdx.y * 128;
    const int bn   = blockIdx.x * 128;

    const __nv_bfloat16* Aop = qkv ? g_a3x : g_a3o;
    const __nv_bfloat16* Bop = qkv ? g_b3q : g_b3o;

    // ldmatrix lane addressing (x4 = four 8x8 b16 matrices)
    // A matrices: [m0-7,k0-7],[m8-15,k0-7],[m0-7,k8-15],[m8-15,k8-15]
    const int a_row_l = (lane & 7) | (((lane >> 3) & 1) << 3);
    const int a_kb    = (lane >> 4) << 4;                       // 0 / 16 B
    // B matrices: [n0-7,k0-7],[n0-7,k8-15],[n8-15,k0-7],[n8-15,k8-15]
    const int b_row_l = (lane & 7) | (((lane >> 4) & 1) << 3);
    const int b_kb    = ((lane >> 3) & 1) << 4;
    const uint32_t axor = (uint32_t)(a_row_l & 7) << 4;
    const uint32_t bxor = (uint32_t)(b_row_l & 7) << 4;

    float acc[4][4][4];
#pragma unroll
    for (int m = 0; m < 4; m++)
#pragma unroll
        for (int n = 0; n < 4; n++)
#pragma unroll
            for (int r = 0; r < 4; r++) acc[m][n][r] = 0.f;

    // --- stage loader: 256 threads x 4 chunks x 2 operands, 16B cp.async,
    //     XOR-swizzled smem rows of 128 B ---
    auto load_stage = [&](int s, int kc) {
        const uint32_t stg = sb + (uint32_t)s * STAGEB;
#pragma unroll
        for (int i = 0; i < 4; i++) {
            const int idx = tid + i * 256;           // 0..1023
            const int row = idx >> 3;
            const int c16 = idx & 7;
            const uint32_t sw = (uint32_t)row * 128 + (((uint32_t)c16 << 4) ^ ((uint32_t)(row & 7) << 4));
            CP_ASYNC16(stg + sw,
                       (const char*)(Aop + (size_t)(bm + row) * K3 + kc) + c16 * 16);
            CP_ASYNC16(stg + TILEB + sw,
                       (const char*)(Bop + (size_t)(bn + row) * K3 + kc) + c16 * 16);
        }
    };

    load_stage(0, 0);      CP_COMMIT();
    load_stage(1, BK);     CP_COMMIT();

    for (int c = 0; c < KC; c++) {
        CP_WAIT(NSTG - 2);
        __syncthreads();

        const int s = c % NSTG;
        const uint32_t sA = sb + (uint32_t)s * STAGEB;
        const uint32_t sB = sA + TILEB;

#pragma unroll
        for (int kk = 0; kk < 4; kk++) {             // 4 k-steps of 16
            uint32_t a[4][4], b[2][4];
#pragma unroll
            for (int mf = 0; mf < 4; mf++)
                LDSM_X4(a[mf][0], a[mf][1], a[mf][2], a[mf][3],
                        sA + (uint32_t)(wm * 64 + mf * 16 + a_row_l) * 128
                           + (((uint32_t)(kk * 32 + a_kb)) ^ axor));
#pragma unroll
            for (int nf2 = 0; nf2 < 2; nf2++)
                LDSM_X4(b[nf2][0], b[nf2][1], b[nf2][2], b[nf2][3],
                        sB + (uint32_t)(wn * 32 + nf2 * 16 + b_row_l) * 128
                           + (((uint32_t)(kk * 32 + b_kb)) ^ bxor));
#pragma unroll
            for (int mf = 0; mf < 4; mf++)
#pragma unroll
                for (int nf = 0; nf < 4; nf++)
                    MMA_BF16(acc[mf][nf], a[mf],
                             b[nf >> 1][(nf & 1) * 2], b[nf >> 1][(nf & 1) * 2 + 1]);
        }

        const int nc = c + NSTG - 1;                 // next chunk to fetch
        if (nc < KC) load_stage(nc % NSTG, nc * BK);
        CP_COMMIT();
    }

    // ------------------ epilogue ------------------
    const int g  = lane >> 2;           // row within fragment
    const int cp = (lane & 3) * 2;      // col pair within fragment

#pragma unroll
    for (int mf = 0; mf < 4; mf++) {
#pragma unroll
        for (int half = 0; half < 2; half++) {
            const int row = bm + wm * 64 + mf * 16 + g + half * 8;
#pragma unroll
            for (int nf = 0; nf < 4; nf++) {
                const int col = bn + wn * 32 + nf * 8 + cp;
                float2 o;
                o.x = acc[mf][nf][half * 2 + 0] + bias[col];
                o.y = acc[mf][nf][half * 2 + 1] + bias[col + 1];
                if (qkv) {
                    const int b  = row >> 11;
                    const int n  = row & 2047;
                    const int pt = col >> 10;
                    const int c1 = col & 1023;
                    const int h  = c1 >> 6;
                    const int hd = c1 & 63;
                    float* dst = (pt == 0) ? g_q : ((pt == 1) ? g_k : g_v);
                    *(float2*)&dst[(((size_t)(b * NHEADS + h)) * SEQ + n) * HDIM + hd] = o;
                } else {
                    *(float2*)&C[(size_t)row * HIDDEN + col] = o;
                }
            }
        }
    }
}

// ---------------------------------------------------------------------------
// Fused flash attention (fp32, online softmax) — unchanged (passing, ~955us)
// ---------------------------------------------------------------------------
#define AST 68
#define ATTN_SMEM (3 * 64 * AST * 4)

__global__ __launch_bounds__(256)
void attn_kernel()
{
    extern __shared__ float sm[];
    float* Qt = sm;
    float* Kt = sm + 64 * AST;
    float* Vs = sm + 2 * 64 * AST;

    const int tid = threadIdx.x;
    const int tx  = tid & 15;
    const int ty  = tid >> 4;
    const int qt  = blockIdx.x;
    const int h   = blockIdx.y;
    const int b   = blockIdx.z;

    const size_t head_off = (size_t)(b * NHEADS + h) * SEQ * HDIM;
    const float* qp = g_q + head_off + (size_t)qt * 64 * HDIM;
    const float* kp = g_k + head_off;
    const float* vp = g_v + head_off;

    const int lr = tid >> 2;
    const int lc = (tid & 3) << 4;

#pragma unroll
    for (int u = 0; u < 4; u++) {
        float4 v = *(const float4*)(qp + (size_t)lr * HDIM + lc + u * 4);
        Qt[(lc + u * 4 + 0) * AST + lr] = v.x;
        Qt[(lc + u * 4 + 1) * AST + lr] = v.y;
        Qt[(lc + u * 4 + 2) * AST + lr] = v.z;
        Qt[(lc + u * 4 + 3) * AST + lr] = v.w;
    }

    float acc[4][4];
    float mrow[4], lrow[4];
#pragma unroll
    for (int i = 0; i < 4; i++) {
        mrow[i] = -3.0e38f;
        lrow[i] = 0.f;
#pragma unroll
        for (int j = 0; j < 4; j++) acc[i][j] = 0.f;
    }

    for (int kt = 0; kt < SEQ / 64; kt++) {
        float4 kreg[4], vreg[4];
        const float* kr = kp + (size_t)kt * 64 * HDIM + (size_t)lr * HDIM + lc;
        const float* vr = vp + (size_t)kt * 64 * HDIM + (size_t)lr * HDIM + lc;
#pragma unroll
        for (int u = 0; u < 4; u++) {
            kreg[u] = *(const float4*)(kr + u * 4);
            vreg[u] = *(const float4*)(vr + u * 4);
        }

        __syncthreads();
#pragma unroll
        for (int u = 0; u < 4; u++) {
            Kt[(lc + u * 4 + 0) * AST + lr] = kreg[u].x;
            Kt[(lc + u * 4 + 1) * AST + lr] = kreg[u].y;
            Kt[(lc + u * 4 + 2) * AST + lr] = kreg[u].z;
            Kt[(lc + u * 4 + 3) * AST + lr] = kreg[u].w;
            *(float4*)(Vs + lr * AST + lc + u * 4) = vreg[u];
        }
        __syncthreads();

        float s[4][4];
#pragma unroll
        for (int i = 0; i < 4; i++)
#pragma unroll
            for (int j = 0; j < 4; j++) s[i][j] = 0.f;

#pragma unroll 8
        for (int d = 0; d < HDIM; d++) {
            float4 q4 = *(const float4*)(Qt + d * AST + ty * 4);
            float4 k4 = *(const float4*)(Kt + d * AST + tx * 4);
            float qa[4] = {q4.x, q4.y, q4.z, q4.w};
            float ka[4] = {k4.x, k4.y, k4.z, k4.w};
#pragma unroll
            for (int i = 0; i < 4; i++)
#pragma unroll
                for (int j = 0; j < 4; j++)
                    s[i][j] = fmaf(qa[i], ka[j], s[i][j]);
        }

#pragma unroll
        for (int i = 0; i < 4; i++) {
#pragma unroll
            for (int j = 0; j < 4; j++) s[i][j] *= 0.125f;
            float rm = fmaxf(fmaxf(s[i][0], s[i][1]), fmaxf(s[i][2], s[i][3]));
#pragma unroll
            for (int off = 8; off > 0; off >>= 1)
                rm = fmaxf(rm, __shfl_xor_sync(0xffffffffu, rm, off, 16));
            const float mn   = fmaxf(mrow[i], rm);
            const float corr = __expf(mrow[i] - mn);
            float rs = 0.f;
#pragma unroll
            for (int j = 0; j < 4; j++) {
                s[i][j] = __expf(s[i][j] - mn);
                rs += s[i][j];
            }
#pragma unroll
            for (int off = 8; off > 0; off >>= 1)
                rs += __shfl_xor_sync(0xffffffffu, rs, off, 16);
            lrow[i] = lrow[i] * corr + rs;
            mrow[i] = mn;
#pragma unroll
            for (int j = 0; j < 4; j++) acc[i][j] *= corr;
        }

        __syncthreads();
#pragma unroll
        for (int i = 0; i < 4; i++) {
            float4 pv = make_float4(s[i][0], s[i][1], s[i][2], s[i][3]);
            *(float4*)(Kt + (ty * 4 + i) * AST + tx * 4) = pv;
        }
        __syncthreads();

#pragma unroll 4
        for (int k0 = 0; k0 < 64; k0 += 4) {
            float P[4][4], V[4][4];
#pragma unroll
            for (int i = 0; i < 4; i++) {
                float4 p4 = *(const float4*)(Kt + (ty * 4 + i) * AST + k0);
                P[i][0] = p4.x; P[i][1] = p4.y; P[i][2] = p4.z; P[i][3] = p4.w;
            }
#pragma unroll
            for (int u = 0; u < 4; u++) {
                float4 v4 = *(const float4*)(Vs + (k0 + u) * AST + tx * 4);
                V[u][0] = v4.x; V[u][1] = v4.y; V[u][2] = v4.z; V[u][3] = v4.w;
            }
#pragma unroll
            for (int i = 0; i < 4; i++)
#pragma unroll
                for (int j = 0; j < 4; j++) {
                    acc[i][j] = fmaf(P[i][0], V[0][j], acc[i][j]);
                    acc[i][j] = fmaf(P[i][1], V[1][j], acc[i][j]);
                    acc[i][j] = fmaf(P[i][2], V[2][j], acc[i][j]);
                    acc[i][j] = fmaf(P[i][3], V[3][j], acc[i][j]);
                }
        }
    }

#pragma unroll
    for (int i = 0; i < 4; i++) {
        const float inv = 1.0f / lrow[i];
        float4 o;
        o.x = acc[i][0] * inv; o.y = acc[i][1] * inv;
        o.z = acc[i][2] * inv; o.w = acc[i][3] * inv;
        const size_t row = (size_t)b * SEQ + qt * 64 + ty * 4 + i;
        *(float4*)&g_ao[row * HIDDEN + h * HDIM + tx * 4] = o;
    }
}

// ---------------------------------------------------------------------------
// Launch
// ---------------------------------------------------------------------------
extern "C" void kernel_launch(void* const* d_in, const int* in_sizes, int n_in,
                              void* d_out, int out_size)
{
    const float* x    = (const float*)d_in[0];
    const float* Wqkv = (const float*)d_in[1];
    const float* bqkv = (const float*)d_in[2];
    const float* Wo   = (const float*)d_in[3];
    const float* bo   = (const float*)d_in[4];
    float* out = (float*)d_out;

    cudaFuncSetAttribute(attn_kernel, cudaFuncAttributeMaxDynamicSharedMemorySize, ATTN_SMEM);
    cudaFuncSetAttribute(gemm_mma,    cudaFuncAttributeMaxDynamicSharedMemorySize, GEMM_SMEM);

    // split inputs into concatenated hi/lo bf16 layout
    split3_kernel<<<MROWS, 256>>>((const float4*)x,    0, MROWS * 256);
    split3_kernel<<<3 * HIDDEN, 256>>>((const float4*)Wqkv, 1, 3 * HIDDEN * 256);
    split3_kernel<<<HIDDEN, 256>>>((const float4*)Wo,  2, HIDDEN * 256);

    // QKV projection (tensor cores via mma.sync) with fused head scatter
    gemm_mma<<<dim3(3 * HIDDEN / 128, MROWS / 128), 256, GEMM_SMEM>>>(bqkv, nullptr, 1);

    // fused attention (fp32)
    attn_kernel<<<dim3(SEQ / 64, NHEADS, BATCH), 256, ATTN_SMEM>>>();

    // split attention output, then O-projection
    split3_kernel<<<MROWS, 256>>>(nullptr, 3, MROWS * 256);
    gemm_mma<<<dim3(HIDDEN / 128, MROWS / 128), 256, GEMM_SMEM>>>(bo, out, 0);
}

// round 10
// speedup vs baseline: 2.6879x; 1.9553x over previous
#include <cuda_runtime.h>
#include <cuda_bf16.h>
#include <cstdint>

#define HIDDEN   1024
#define BATCH    2
#define SEQ      2048
#define NHEADS   16
#define HDIM     64
#define MROWS    (BATCH * SEQ)   // 4096
#define KDIM     1024
#define K3       (3 * KDIM)      // 3072 (split-bf16 concatenated K)

// ---------------------------------------------------------------------------
// Scratch (static device globals — no runtime allocation allowed)
// ---------------------------------------------------------------------------
__device__ __align__(256) float g_ao[MROWS * HIDDEN];

// Split-bf16 concatenated GEMM operands
__device__ __align__(256) __nv_bfloat16 g_a3x[MROWS * K3];        // x split
__device__ __align__(256) __nv_bfloat16 g_a3o[MROWS * K3];        // attn-out split
__device__ __align__(256) __nv_bfloat16 g_b3q[3 * HIDDEN * K3];   // W_qkv split
__device__ __align__(256) __nv_bfloat16 g_b3o[HIDDEN * K3];       // W_o split

// Attention operands (written by QKV GEMM epilogue):
//   g_q2/g_k2: [B*H][N][ hi(64) | lo(64) ] bf16
//   g_vth/g_vtl: [B*H][d=64][N] bf16 (transposed V, hi / lo)
__device__ __align__(256) __nv_bfloat16 g_q2 [BATCH * NHEADS * SEQ * 128];
__device__ __align__(256) __nv_bfloat16 g_k2 [BATCH * NHEADS * SEQ * 128];
__device__ __align__(256) __nv_bfloat16 g_vth[BATCH * NHEADS * 64 * SEQ];
__device__ __align__(256) __nv_bfloat16 g_vtl[BATCH * NHEADS * 64 * SEQ];

// ---------------------------------------------------------------------------
// PTX helpers (baseline sm_100 safe)
// ---------------------------------------------------------------------------
__device__ __forceinline__ uint32_t smem_u32(const void* p) {
    uint32_t a;
    asm("{ .reg .u64 t; cvta.to.shared.u64 t, %1; cvt.u32.u64 %0, t; }" : "=r"(a) : "l"(p));
    return a;
}
__device__ __forceinline__ float ex2f(float x) {
    float y; asm("ex2.approx.ftz.f32 %0, %1;" : "=f"(y) : "f"(x)); return y;
}

#define CP_ASYNC16(dst, src) \
    asm volatile("cp.async.cg.shared.global [%0], [%1], 16;" :: "r"(dst), "l"(src) : "memory")
#define CP_COMMIT() asm volatile("cp.async.commit_group;" ::: "memory")
#define CP_WAIT(n)  asm volatile("cp.async.wait_group %0;" :: "n"(n) : "memory")

#define LDSM_X4(r0, r1, r2, r3, addr) \
    asm volatile("ldmatrix.sync.aligned.m8n8.x4.shared.b16 {%0,%1,%2,%3}, [%4];" \
        : "=r"(r0), "=r"(r1), "=r"(r2), "=r"(r3) : "r"(addr))

#define MMA_BF16(d, a, b0, b1) \
    asm volatile("mma.sync.aligned.m16n8k16.row.col.f32.bf16.bf16.f32 " \
        "{%0,%1,%2,%3}, {%4,%5,%6,%7}, {%8,%9}, {%0,%1,%2,%3};" \
        : "+f"((d)[0]), "+f"((d)[1]), "+f"((d)[2]), "+f"((d)[3]) \
        : "r"((a)[0]), "r"((a)[1]), "r"((a)[2]), "r"((a)[3]), "r"(b0), "r"(b1))

#define PACK_BF16X2(dst, lo, hi) \
    asm("cvt.rn.bf16x2.f32 %0, %1, %2;" : "=r"(dst) : "f"(hi), "f"(lo))

// ---------------------------------------------------------------------------
// fp32 -> split-bf16 concatenated layout (unchanged from round 9).
// dst_sel: 0 = g_a3x (src=x), 1 = g_b3q, 2 = g_b3o, 3 = g_a3o (src = g_ao)
// A layout: hi @ c, c+2048 ; lo @ c+1024.   B layout: hi @ c, c+1024 ; lo @ c+2048
// ---------------------------------------------------------------------------
__global__ void split3_kernel(const float4* __restrict__ src, int dst_sel, int n4)
{
    int i = blockIdx.x * blockDim.x + threadIdx.x;
    if (i >= n4) return;
    const float4* s = src ? src : (const float4*)g_ao;
    __nv_bfloat16* dst = (dst_sel == 0) ? g_a3x :
                         (dst_sel == 1) ? g_b3q :
                         (dst_sel == 2) ? g_b3o : g_a3o;
    const int off_hi1 = (dst_sel == 1 || dst_sel == 2) ? 1024 : 2048;
    const int off_lo  = (dst_sel == 1 || dst_sel == 2) ? 2048 : 1024;

    const int r = i >> 8;
    const int c = (i & 255) << 2;

    float4 v = s[i];
    __nv_bfloat162 hA = __floats2bfloat162_rn(v.x, v.y);
    __nv_bfloat162 hB = __floats2bfloat162_rn(v.z, v.w);
    __nv_bfloat162 lA = __floats2bfloat162_rn(v.x - __low2float(hA), v.y - __high2float(hA));
    __nv_bfloat162 lB = __floats2bfloat162_rn(v.z - __low2float(hB), v.w - __high2float(hB));
    uint2 H, L;
    H.x = *reinterpret_cast<const uint32_t*>(&hA);
    H.y = *reinterpret_cast<const uint32_t*>(&hB);
    L.x = *reinterpret_cast<const uint32_t*>(&lA);
    L.y = *reinterpret_cast<const uint32_t*>(&lB);

    uint2* base = (uint2*)(dst + (size_t)r * K3);
    base[(c) >> 2]           = H;
    base[(off_hi1 + c) >> 2] = H;
    base[(off_lo  + c) >> 2] = L;
}

// ---------------------------------------------------------------------------
// bf16 mma.sync GEMM (round-9 core, epilogue updated):
// qkv=1: writes split Q/K into g_q2/g_k2 and transposed split V into g_vth/g_vtl
// qkv=0: plain C write + bias
// ---------------------------------------------------------------------------
#define BK      64
#define NSTG    3
#define KC      (K3 / BK)          // 48
#define TILEB   (128 * BK * 2)     // 16384
#define STAGEB  (2 * TILEB)        // 32768
#define GEMM_SMEM (NSTG * STAGEB)  // 98304

__global__ __launch_bounds__(256, 1)
void gemm_mma(const float* __restrict__ bias, float* __restrict__ C, int qkv)
{
    extern __shared__ __align__(1024) char smem[];
    const uint32_t sb = smem_u32(smem);

    const int tid  = threadIdx.x;
    const int lane = tid & 31;
    const int wid  = tid >> 5;
    const int wm   = wid & 1;
    const int wn   = wid >> 1;
    const int bm   = blockIdx.y * 128;
    const int bn   = blockIdx.x * 128;

    const __nv_bfloat16* Aop = qkv ? g_a3x : g_a3o;
    const __nv_bfloat16* Bop = qkv ? g_b3q : g_b3o;

    const int a_row_l = (lane & 7) | (((lane >> 3) & 1) << 3);
    const int a_kb    = (lane >> 4) << 4;
    const int b_row_l = (lane & 7) | (((lane >> 4) & 1) << 3);
    const int b_kb    = ((lane >> 3) & 1) << 4;
    const uint32_t axor = (uint32_t)(a_row_l & 7) << 4;
    const uint32_t bxor = (uint32_t)(b_row_l & 7) << 4;

    float acc[4][4][4];
#pragma unroll
    for (int m = 0; m < 4; m++)
#pragma unroll
        for (int n = 0; n < 4; n++)
#pragma unroll
            for (int r = 0; r < 4; r++) acc[m][n][r] = 0.f;

    auto load_stage = [&](int s, int kc) {
        const uint32_t stg = sb + (uint32_t)s * STAGEB;
#pragma unroll
        for (int i = 0; i < 4; i++) {
            const int idx = tid + i * 256;
            const int row = idx >> 3;
            const int c16 = idx & 7;
            const uint32_t sw = (uint32_t)row * 128 + (((uint32_t)c16 << 4) ^ ((uint32_t)(row & 7) << 4));
            CP_ASYNC16(stg + sw,
                       (const char*)(Aop + (size_t)(bm + row) * K3 + kc) + c16 * 16);
            CP_ASYNC16(stg + TILEB + sw,
                       (const char*)(Bop + (size_t)(bn + row) * K3 + kc) + c16 * 16);
        }
    };

    load_stage(0, 0);      CP_COMMIT();
    load_stage(1, BK);     CP_COMMIT();

    for (int c = 0; c < KC; c++) {
        CP_WAIT(NSTG - 2);
        __syncthreads();

        const int s = c % NSTG;
        const uint32_t sA = sb + (uint32_t)s * STAGEB;
        const uint32_t sB = sA + TILEB;

#pragma unroll
        for (int kk = 0; kk < 4; kk++) {
            uint32_t a[4][4], b[2][4];
#pragma unroll
            for (int mf = 0; mf < 4; mf++)
                LDSM_X4(a[mf][0], a[mf][1], a[mf][2], a[mf][3],
                        sA + (uint32_t)(wm * 64 + mf * 16 + a_row_l) * 128
                           + (((uint32_t)(kk * 32 + a_kb)) ^ axor));
#pragma unroll
            for (int nf2 = 0; nf2 < 2; nf2++)
                LDSM_X4(b[nf2][0], b[nf2][1], b[nf2][2], b[nf2][3],
                        sB + (uint32_t)(wn * 32 + nf2 * 16 + b_row_l) * 128
                           + (((uint32_t)(kk * 32 + b_kb)) ^ bxor));
#pragma unroll
            for (int mf = 0; mf < 4; mf++)
#pragma unroll
                for (int nf = 0; nf < 4; nf++)
                    MMA_BF16(acc[mf][nf], a[mf],
                             b[nf >> 1][(nf & 1) * 2], b[nf >> 1][(nf & 1) * 2 + 1]);
        }

        const int nc = c + NSTG - 1;
        if (nc < KC) load_stage(nc % NSTG, nc * BK);
        CP_COMMIT();
    }

    // ------------------ epilogue ------------------
    const int g  = lane >> 2;
    const int cp = (lane & 3) * 2;

#pragma unroll
    for (int mf = 0; mf < 4; mf++) {
#pragma unroll
        for (int half = 0; half < 2; half++) {
            const int row = bm + wm * 64 + mf * 16 + g + half * 8;
#pragma unroll
            for (int nf = 0; nf < 4; nf++) {
                const int col = bn + wn * 32 + nf * 8 + cp;
                float2 o;
                o.x = acc[mf][nf][half * 2 + 0] + bias[col];
                o.y = acc[mf][nf][half * 2 + 1] + bias[col + 1];
                if (qkv) {
                    const int bb = row >> 11;
                    const int n  = row & 2047;
                    const int pt = col >> 10;
                    const int c1 = col & 1023;
                    const int hh = c1 >> 6;
                    const int hd = c1 & 63;          // even
                    const int bh = bb * NHEADS + hh;
                    __nv_bfloat162 hv = __floats2bfloat162_rn(o.x, o.y);
                    __nv_bfloat162 lv = __floats2bfloat162_rn(
                        o.x - __bfloat162float(hv.x), o.y - __bfloat162float(hv.y));
                    if (pt < 2) {
                        __nv_bfloat16* dst = pt ? g_k2 : g_q2;
                        const size_t base = ((size_t)bh * SEQ + n) * 128;
                        *(__nv_bfloat162*)&dst[base + hd]      = hv;
                        *(__nv_bfloat162*)&dst[base + 64 + hd] = lv;
                    } else {
                        const size_t vb = ((size_t)bh * 64 + hd) * SEQ + n;
                        g_vth[vb]       = hv.x;
                        g_vth[vb + SEQ] = hv.y;
                        g_vtl[vb]       = lv.x;
                        g_vtl[vb + SEQ] = lv.y;
                    }
                } else {
                    *(float2*)&C[(size_t)row * HIDDEN + col] = o;
                }
            }
        }
    }
}

// ---------------------------------------------------------------------------
// Flash attention on mma.sync bf16 (3-term split QK and PV, fp32 softmax).
// Grid (16,16,2); 256 threads = 8 warps, each warp owns 16 query rows x all
// 64 keys of the tile. Q tile resident in smem; K/V tiles 3-stage cp.async.
// smem: q2 32KB + 3 stages x (k2 16KB + vt 16KB) = 128KB.
// ---------------------------------------------------------------------------
#define NT        (SEQ / 64)       // 32 key tiles
#define ASTG_OFF  32768
#define ASTG_SZ   32768
#define ATTN2_SMEM (32768 + 3 * ASTG_SZ)   // 131072

__global__ __launch_bounds__(256, 1)
void attn_mma()
{
    extern __shared__ __align__(1024) char smem[];
    const uint32_t sb = smem_u32(smem);
    const int tid = threadIdx.x, lane = tid & 31, wid = tid >> 5;
    const int qt = blockIdx.x, h = blockIdx.y, b = blockIdx.z;
    const int bh = b * NHEADS + h;

    const __nv_bfloat16* q2p = g_q2 + ((size_t)bh * SEQ + qt * 128) * 128;
    const __nv_bfloat16* k2p = g_k2 + (size_t)bh * SEQ * 128;
    const __nv_bfloat16* vhp = g_vth + (size_t)bh * 64 * SEQ;
    const __nv_bfloat16* vlp = g_vtl + (size_t)bh * 64 * SEQ;

    auto load_stage = [&](int kt) {
        const uint32_t stg = sb + ASTG_OFF + (uint32_t)(kt % 3) * ASTG_SZ;
#pragma unroll
        for (int i = 0; i < 8; i++) {
            const int idx = tid + i * 256;                 // 0..2047
            if (idx < 1024) {                              // k2: 64 rows x 16 chunks
                const int row = idx >> 4, c16 = idx & 15;
                CP_ASYNC16(stg + row * 256 + (((uint32_t)c16 << 4) ^ ((uint32_t)(row & 7) << 4)),
                           (const char*)(k2p + (size_t)(kt * 64 + row) * 128) + c16 * 16);
            } else {                                       // vt: 64 d-rows x [Vh 8 | Vl 8]
                const int j = idx - 1024;
                const int row = j >> 4, c16 = j & 15;
                const __nv_bfloat16* src = (c16 < 8) ? vhp : vlp;
                CP_ASYNC16(stg + 16384 + row * 256 + (((uint32_t)c16 << 4) ^ ((uint32_t)(row & 7) << 4)),
                           (const char*)(src + (size_t)row * SEQ + kt * 64) + (c16 & 7) * 16);
            }
        }
    };

    // Q tile: 128 rows x 16 chunks (part of first commit group)
#pragma unroll
    for (int i = 0; i < 8; i++) {
        const int idx = tid + i * 256;
        const int row = idx >> 4, c16 = idx & 15;
        CP_ASYNC16(sb + row * 256 + (((uint32_t)c16 << 4) ^ ((uint32_t)(row & 7) << 4)),
                   (const char*)(q2p + (size_t)row * 128) + c16 * 16);
    }
    load_stage(0); CP_COMMIT();
    load_stage(1); CP_COMMIT();

    const int a_row = wid * 16 + ((lane & 7) | (((lane >> 3) & 1) << 3));
    const int a_kb  = lane >> 4;                  // 0/1 (16B half of k16)
    const int b_rl  = (lane & 7) | (((lane >> 4) & 1) << 3);
    const int b_kb  = (lane >> 3) & 1;
    const uint32_t a_sw = (uint32_t)(a_row & 7) << 4;
    const uint32_t qbase = sb + (uint32_t)a_row * 256;

    float oacc[8][4];
#pragma unroll
    for (int nf = 0; nf < 8; nf++)
#pragma unroll
        for (int e = 0; e < 4; e++) oacc[nf][e] = 0.f;
    float m0 = -1e30f, m1 = -1e30f, l0 = 0.f, l1 = 0.f;
    const float CS = 0.18033688011f;              // 0.125 * log2(e)

    for (int kt = 0; kt < NT; kt++) {
        if (kt + 2 < NT) { CP_WAIT(1); } else { CP_WAIT(0); }
        __syncthreads();
        if (kt + 2 < NT) { load_stage(kt + 2); CP_COMMIT(); }

        const uint32_t sk = sb + ASTG_OFF + (uint32_t)(kt % 3) * ASTG_SZ;
        const uint32_t sv = sk + 16384;

        // ---- S = Qh·Kh + Ql·Kh + Qh·Kl ----
        float s[8][4];
#pragma unroll
        for (int nf = 0; nf < 8; nf++)
#pragma unroll
            for (int e = 0; e < 4; e++) s[nf][e] = 0.f;

#pragma unroll
        for (int kk = 0; kk < 4; kk++) {
            uint32_t aqh[4], aql[4], bk[4][4];
            LDSM_X4(aqh[0], aqh[1], aqh[2], aqh[3],
                    qbase + (((uint32_t)(kk * 2 + a_kb) << 4) ^ a_sw));
            LDSM_X4(aql[0], aql[1], aql[2], aql[3],
                    qbase + (((uint32_t)(8 + kk * 2 + a_kb) << 4) ^ a_sw));
#pragma unroll
            for (int nb = 0; nb < 4; nb++) {
                const int br = nb * 16 + b_rl;
                LDSM_X4(bk[nb][0], bk[nb][1], bk[nb][2], bk[nb][3],
                        sk + (uint32_t)br * 256 + (((uint32_t)(kk * 2 + b_kb) << 4) ^ ((uint32_t)(br & 7) << 4)));
            }
#pragma unroll
            for (int nf = 0; nf < 8; nf++) {
                MMA_BF16(s[nf], aqh, bk[nf >> 1][(nf & 1) * 2], bk[nf >> 1][(nf & 1) * 2 + 1]);
                MMA_BF16(s[nf], aql, bk[nf >> 1][(nf & 1) * 2], bk[nf >> 1][(nf & 1) * 2 + 1]);
            }
        }
#pragma unroll
        for (int kk = 0; kk < 4; kk++) {           // + Qh·Kl
            uint32_t aqh[4], bk[4][4];
            LDSM_X4(aqh[0], aqh[1], aqh[2], aqh[3],
                    qbase + (((uint32_t)(kk * 2 + a_kb) << 4) ^ a_sw));
#pragma unroll
            for (int nb = 0; nb < 4; nb++) {
                const int br = nb * 16 + b_rl;
                LDSM_X4(bk[nb][0], bk[nb][1], bk[nb][2], bk[nb][3],
                        sk + (uint32_t)br * 256 + (((uint32_t)(8 + kk * 2 + b_kb) << 4) ^ ((uint32_t)(br & 7) << 4)));
            }
#pragma unroll
            for (int nf = 0; nf < 8; nf++)
                MMA_BF16(s[nf], aqh, bk[nf >> 1][(nf & 1) * 2], bk[nf >> 1][(nf & 1) * 2 + 1]);
        }

        // ---- online softmax (fp32) ----
        float rm0 = s[0][0], rm1 = s[0][2];
#pragma unroll
        for (int nf = 0; nf < 8; nf++) {
            rm0 = fmaxf(rm0, fmaxf(s[nf][0], s[nf][1]));
            rm1 = fmaxf(rm1, fmaxf(s[nf][2], s[nf][3]));
        }
        rm0 = fmaxf(rm0, __shfl_xor_sync(0xffffffffu, rm0, 1));
        rm0 = fmaxf(rm0, __shfl_xor_sync(0xffffffffu, rm0, 2));
        rm1 = fmaxf(rm1, __shfl_xor_sync(0xffffffffu, rm1, 1));
        rm1 = fmaxf(rm1, __shfl_xor_sync(0xffffffffu, rm1, 2));
        const float mn0 = fmaxf(m0, rm0 * CS);
        const float mn1 = fmaxf(m1, rm1 * CS);
        const float cr0 = ex2f(m0 - mn0);
        const float cr1 = ex2f(m1 - mn1);
        float sum0 = 0.f, sum1 = 0.f;
#pragma unroll
        for (int nf = 0; nf < 8; nf++) {
            s[nf][0] = ex2f(fmaf(s[nf][0], CS, -mn0));
            s[nf][1] = ex2f(fmaf(s[nf][1], CS, -mn0));
            s[nf][2] = ex2f(fmaf(s[nf][2], CS, -mn1));
            s[nf][3] = ex2f(fmaf(s[nf][3], CS, -mn1));
            sum0 += s[nf][0] + s[nf][1];
            sum1 += s[nf][2] + s[nf][3];
        }
        sum0 += __shfl_xor_sync(0xffffffffu, sum0, 1);
        sum0 += __shfl_xor_sync(0xffffffffu, sum0, 2);
        sum1 += __shfl_xor_sync(0xffffffffu, sum1, 1);
        sum1 += __shfl_xor_sync(0xffffffffu, sum1, 2);
        l0 = l0 * cr0 + sum0;  l1 = l1 * cr1 + sum1;
        m0 = mn0;  m1 = mn1;
#pragma unroll
        for (int nf = 0; nf < 8; nf++) {
            oacc[nf][0] *= cr0; oacc[nf][1] *= cr0;
            oacc[nf][2] *= cr1; oacc[nf][3] *= cr1;
        }

        // ---- P -> bf16 hi/lo A-fragments (in registers) ----
        uint32_t ph[4][4], pl[4][4];
#pragma unroll
        for (int t = 0; t < 4; t++) {
#pragma unroll
            for (int hf = 0; hf < 2; hf++) {
                const int j = 2 * t + hf;
                uint32_t hp0, hp1, lp0, lp1;
                PACK_BF16X2(hp0, s[j][0], s[j][1]);
                PACK_BF16X2(hp1, s[j][2], s[j][3]);
                const float r0a = s[j][0] - __uint_as_float(hp0 << 16);
                const float r0b = s[j][1] - __uint_as_float(hp0 & 0xFFFF0000u);
                const float r1a = s[j][2] - __uint_as_float(hp1 << 16);
                const float r1b = s[j][3] - __uint_as_float(hp1 & 0xFFFF0000u);
                PACK_BF16X2(lp0, r0a, r0b);
                PACK_BF16X2(lp1, r1a, r1b);
                ph[t][hf * 2 + 0] = hp0;  ph[t][hf * 2 + 1] = hp1;
                pl[t][hf * 2 + 0] = lp0;  pl[t][hf * 2 + 1] = lp1;
            }
        }

        // ---- O += Ph·Vh + Pl·Vh + Ph·Vl ----
#pragma unroll
        for (int t = 0; t < 4; t++) {
            uint32_t bv[4][4];
#pragma unroll
            for (int nb = 0; nb < 4; nb++) {
                const int br = nb * 16 + b_rl;
                LDSM_X4(bv[nb][0], bv[nb][1], bv[nb][2], bv[nb][3],
                        sv + (uint32_t)br * 256 + (((uint32_t)(t * 2 + b_kb) << 4) ^ ((uint32_t)(br & 7) << 4)));
            }
#pragma unroll
            for (int nf = 0; nf < 8; nf++) {
                MMA_BF16(oacc[nf], ph[t], bv[nf >> 1][(nf & 1) * 2], bv[nf >> 1][(nf & 1) * 2 + 1]);
                MMA_BF16(oacc[nf], pl[t], bv[nf >> 1][(nf & 1) * 2], bv[nf >> 1][(nf & 1) * 2 + 1]);
            }
        }
#pragma unroll
        for (int t = 0; t < 4; t++) {
            uint32_t bv[4][4];
#pragma unroll
            for (int nb = 0; nb < 4; nb++) {
                const int br = nb * 16 + b_rl;
                LDSM_X4(bv[nb][0], bv[nb][1], bv[nb][2], bv[nb][3],
                        sv + (uint32_t)br * 256 + (((uint32_t)(8 + t * 2 + b_kb) << 4) ^ ((uint32_t)(br & 7) << 4)));
            }
#pragma unroll
            for (int nf = 0; nf < 8; nf++)
                MMA_BF16(oacc[nf], ph[t], bv[nf >> 1][(nf & 1) * 2], bv[nf >> 1][(nf & 1) * 2 + 1]);
        }
    }

    // ---- epilogue: normalize, write g_ao ----
    const int g = lane >> 2, cp2 = (lane & 3) * 2;
    const float i0 = 1.f / l0, i1 = 1.f / l1;
    const size_t r0 = (size_t)b * SEQ + qt * 128 + wid * 16 + g;
#pragma unroll
    for (int nf = 0; nf < 8; nf++) {
        const int col = h * 64 + nf * 8 + cp2;
        float2 u, v;
        u.x = oacc[nf][0] * i0;  u.y = oacc[nf][1] * i0;
        v.x = oacc[nf][2] * i1;  v.y = oacc[nf][3] * i1;
        *(float2*)&g_ao[r0 * HIDDEN + col]       = u;
        *(float2*)&g_ao[(r0 + 8) * HIDDEN + col] = v;
    }
}

// ---------------------------------------------------------------------------
// Launch
// ---------------------------------------------------------------------------
extern "C" void kernel_launch(void* const* d_in, const int* in_sizes, int n_in,
                              void* d_out, int out_size)
{
    const float* x    = (const float*)d_in[0];
    const float* Wqkv = (const float*)d_in[1];
    const float* bqkv = (const float*)d_in[2];
    const float* Wo   = (const float*)d_in[3];
    const float* bo   = (const float*)d_in[4];
    float* out = (float*)d_out;

    cudaFuncSetAttribute(gemm_mma, cudaFuncAttributeMaxDynamicSharedMemorySize, GEMM_SMEM);
    cudaFuncSetAttribute(attn_mma, cudaFuncAttributeMaxDynamicSharedMemorySize, ATTN2_SMEM);

    // split inputs into concatenated hi/lo bf16 layout
    split3_kernel<<<MROWS, 256>>>((const float4*)x,    0, MROWS * 256);
    split3_kernel<<<3 * HIDDEN, 256>>>((const float4*)Wqkv, 1, 3 * HIDDEN * 256);
    split3_kernel<<<HIDDEN, 256>>>((const float4*)Wo,  2, HIDDEN * 256);

    // QKV projection -> split attention operands (q2/k2/vth/vtl)
    gemm_mma<<<dim3(3 * HIDDEN / 128, MROWS / 128), 256, GEMM_SMEM>>>(bqkv, nullptr, 1);

    // attention on tensor cores
    attn_mma<<<dim3(SEQ / 128, NHEADS, BATCH), 256, ATTN2_SMEM>>>();

    // split attention output, then O-projection
    split3_kernel<<<MROWS, 256>>>(nullptr, 3, MROWS * 256);
    gemm_mma<<<dim3(HIDDEN / 128, MROWS / 128), 256, GEMM_SMEM>>>(bo, out, 0);
}